// round 1
// baseline (speedup 1.0000x reference)
#include <cuda_runtime.h>
#include <math.h>

// YOLO-v2-style loss over [BATCH, S, S, N] with S=7, B=2, C=4, N=14.
// One thread per grid cell (BATCH*S*S = 802816 cells). Each cell reads
// 14 pred + 14 target contiguous floats (56B, 8-byte aligned -> float2).
// Block-reduce partial sums, one atomicAdd per block into d_out[0].

static __device__ __forceinline__ float block_reduce(float v) {
    // warp reduce
    #pragma unroll
    for (int off = 16; off > 0; off >>= 1)
        v += __shfl_down_sync(0xFFFFFFFFu, v, off);
    __shared__ float warp_sums[8];  // up to 256 threads = 8 warps
    int lane = threadIdx.x & 31;
    int wid  = threadIdx.x >> 5;
    if (lane == 0) warp_sums[wid] = v;
    __syncthreads();
    if (wid == 0) {
        int nw = (blockDim.x + 31) >> 5;
        v = (lane < nw) ? warp_sums[lane] : 0.0f;
        #pragma unroll
        for (int off = 4; off > 0; off >>= 1)
            v += __shfl_down_sync(0xFFFFFFFFu, v, off);
    }
    return v;  // valid on thread 0
}

__global__ void zero_out_kernel(float* out) {
    if (threadIdx.x == 0 && blockIdx.x == 0) out[0] = 0.0f;
}

__global__ __launch_bounds__(256)
void yolo_loss_kernel(const float* __restrict__ pred,
                      const float* __restrict__ tgt,
                      float* __restrict__ out,
                      int cells) {
    const float INV_S = 1.0f / 7.0f;
    int i = blockIdx.x * blockDim.x + threadIdx.x;
    float cell_sum = 0.0f;

    if (i < cells) {
        // Load 14 floats each via float2 (56B per cell, 8B aligned).
        float p[14], t[14];
        const float2* p2 = reinterpret_cast<const float2*>(pred + (size_t)i * 14);
        const float2* t2 = reinterpret_cast<const float2*>(tgt  + (size_t)i * 14);
        #pragma unroll
        for (int j = 0; j < 7; j++) {
            float2 v = __ldg(&p2[j]); p[2*j] = v.x; p[2*j+1] = v.y;
        }
        #pragma unroll
        for (int j = 0; j < 7; j++) {
            float2 v = __ldg(&t2[j]); t[2*j] = v.x; t[2*j+1] = v.y;
        }

        float conf_t = t[4];
        float coord  = (conf_t > 0.0f) ? 1.0f : 0.0f;

        // target box 0 corners
        float t_cx = t[0] * INV_S, t_cy = t[1] * INV_S;
        float t_w  = t[2],          t_h  = t[3];
        float t_l  = t_cx - 0.5f * t_w, t_r = t_cx + 0.5f * t_w;
        float t_t  = t_cy - 0.5f * t_h, t_b = t_cy + 0.5f * t_h;
        float area_t = t_w * t_h;

        float iou[2];
        #pragma unroll
        for (int b = 0; b < 2; b++) {
            int bs = 5 * b;
            float cx = p[bs]   * INV_S;
            float cy = p[bs+1] * INV_S;
            float w  = p[bs+2];
            float h  = p[bs+3];
            float pl = cx - 0.5f * w, pr = cx + 0.5f * w;
            float pt = cy - 0.5f * h, pb = cy + 0.5f * h;
            float il = fmaxf(pl, t_l), ir = fminf(pr, t_r);
            float it = fmaxf(pt, t_t), ib = fminf(pb, t_b);
            float iw = fmaxf(ir - il, 0.0f);
            float ih = fmaxf(ib - it, 0.0f);
            float inter = iw * ih;
            float area_p = w * h;
            iou[b] = inter / (area_p + area_t - inter);
        }

        // argmax with first-index tie-break (strict >)
        int   idx     = (iou[1] > iou[0]) ? 1 : 0;
        float max_iou = fmaxf(iou[0], iou[1]);
        int   rb      = 5 * idx;

        // box losses (only when coord > 0)
        float dxy0 = p[rb]   - t[rb];
        float dxy1 = p[rb+1] - t[rb+1];
        float loss_xy = dxy0 * dxy0 + dxy1 * dxy1;

        float dw = sqrtf(p[rb+2]) - sqrtf(t[rb+2]);
        float dh = sqrtf(p[rb+3]) - sqrtf(t[rb+3]);
        float loss_wh = dw * dw + dh * dh;

        float dob = p[rb+4] - max_iou;
        float loss_obj = dob * dob;

        // class BCE over channels 10..13
        float loss_cls = 0.0f;
        #pragma unroll
        for (int c = 10; c < 14; c++) {
            float pc = p[c], tc = t[c];
            loss_cls -= tc * logf(pc) + (1.0f - tc) * logf(1.0f - pc);
        }

        cell_sum = coord * (loss_xy + loss_wh + loss_obj + loss_cls);

        // distribution-focal-ish term, unmasked
        float q  = conf_t;
        float pp = p[4];
        float alpha = (1.0f - q) / (1.0f - pp);
        cell_sum += alpha * (pp - q) * logf(pp) + (q - pp) * logf(1.0f - pp);
    }

    float bsum = block_reduce(cell_sum);
    if (threadIdx.x == 0) atomicAdd(out, bsum);
}

extern "C" void kernel_launch(void* const* d_in, const int* in_sizes, int n_in,
                              void* d_out, int out_size) {
    const float* pred = (const float*)d_in[0];
    const float* tgt  = (const float*)d_in[1];
    float* out = (float*)d_out;

    int cells = in_sizes[0] / 14;

    zero_out_kernel<<<1, 32>>>(out);
    int threads = 256;
    int blocks  = (cells + threads - 1) / threads;
    yolo_loss_kernel<<<blocks, threads>>>(pred, tgt, out, cells);
}

// round 2
// speedup vs baseline: 1.3735x; 1.3735x over previous
#include <cuda_runtime.h>
#include <math.h>

// YOLO loss over [16384, 7, 7, 14] fp32 (pred + target, ~90 MB read total).
// 2 cells per thread => 112 B per thread per array = 7 x float4 (16B aligned).
// Fast-math __logf / __fdividef (tolerance is 1e-3; these are ~1e-6).
// Per-block partial sums + last-block-done final reduction (single launch).

#define THREADS 256
#define CELLS_PER_THREAD 2
#define CELLS_PER_BLOCK (THREADS * CELLS_PER_THREAD)
#define MAX_BLOCKS 8192

__device__ float        g_partials[MAX_BLOCKS];
__device__ unsigned int g_count = 0;

static __device__ __forceinline__ float block_reduce(float v) {
    #pragma unroll
    for (int off = 16; off > 0; off >>= 1)
        v += __shfl_down_sync(0xFFFFFFFFu, v, off);
    __shared__ float warp_sums[THREADS / 32];
    int lane = threadIdx.x & 31;
    int wid  = threadIdx.x >> 5;
    if (lane == 0) warp_sums[wid] = v;
    __syncthreads();
    if (wid == 0) {
        v = (lane < (THREADS / 32)) ? warp_sums[lane] : 0.0f;
        #pragma unroll
        for (int off = (THREADS / 64); off > 0; off >>= 1)
            v += __shfl_down_sync(0xFFFFFFFFu, v, off);
    }
    return v;  // valid on thread 0
}

// Loss for one cell; p/t are 14 compile-time-indexed register values.
static __device__ __forceinline__ float cell_loss(const float* p, const float* t) {
    const float INV_S = 1.0f / 7.0f;

    float conf_t = t[4];
    float coord  = (conf_t > 0.0f) ? 1.0f : 0.0f;

    // target box 0 corners
    float t_cx = t[0] * INV_S, t_cy = t[1] * INV_S;
    float t_w  = t[2],          t_h  = t[3];
    float t_l  = t_cx - 0.5f * t_w, t_r = t_cx + 0.5f * t_w;
    float t_t  = t_cy - 0.5f * t_h, t_b = t_cy + 0.5f * t_h;
    float area_t = t_w * t_h;

    float iou[2];
    #pragma unroll
    for (int b = 0; b < 2; b++) {
        float cx = p[5*b]   * INV_S;
        float cy = p[5*b+1] * INV_S;
        float w  = p[5*b+2];
        float h  = p[5*b+3];
        float pl = cx - 0.5f * w, pr = cx + 0.5f * w;
        float pt = cy - 0.5f * h, pb = cy + 0.5f * h;
        float iw = fmaxf(fminf(pr, t_r) - fmaxf(pl, t_l), 0.0f);
        float ih = fmaxf(fminf(pb, t_b) - fmaxf(pt, t_t), 0.0f);
        float inter = iw * ih;
        iou[b] = __fdividef(inter, w * h + area_t - inter);
    }

    // argmax, first-index tie-break (strict >)
    bool  sec     = iou[1] > iou[0];
    float max_iou = fmaxf(iou[0], iou[1]);

    // responsible box via selects (no dynamic register indexing)
    float rp0 = sec ? p[5] : p[0];
    float rp1 = sec ? p[6] : p[1];
    float rp2 = sec ? p[7] : p[2];
    float rp3 = sec ? p[8] : p[3];
    float rp4 = sec ? p[9] : p[4];
    float rt0 = sec ? t[5] : t[0];
    float rt1 = sec ? t[6] : t[1];
    float rt2 = sec ? t[7] : t[2];
    float rt3 = sec ? t[8] : t[3];

    float d0 = rp0 - rt0;
    float d1 = rp1 - rt1;
    float loss_xy = d0 * d0 + d1 * d1;

    float dw = sqrtf(rp2) - sqrtf(rt2);
    float dh = sqrtf(rp3) - sqrtf(rt3);
    float loss_wh = dw * dw + dh * dh;

    float dob = rp4 - max_iou;
    float loss_obj = dob * dob;

    // class BCE over channels 10..13
    float loss_cls = 0.0f;
    #pragma unroll
    for (int c = 10; c < 14; c++) {
        float pc = p[c], tc = t[c];
        loss_cls -= tc * __logf(pc) + (1.0f - tc) * __logf(1.0f - pc);
    }

    float s = coord * (loss_xy + loss_wh + loss_obj + loss_cls);

    // df term, unmasked over all cells
    float q  = conf_t;
    float pp = p[4];
    float alpha = __fdividef(1.0f - q, 1.0f - pp);
    s += alpha * (pp - q) * __logf(pp) + (q - pp) * __logf(1.0f - pp);
    return s;
}

__global__ __launch_bounds__(THREADS)
void yolo_loss_kernel(const float* __restrict__ pred,
                      const float* __restrict__ tgt,
                      float* __restrict__ out,
                      int cells, int nblocks) {
    int tid  = threadIdx.x;
    int pair = blockIdx.x * THREADS + tid;   // cell pair index
    float sum = 0.0f;

    if (pair * 2 < cells) {
        // 2 cells = 28 floats = 112 B = 7 float4, 16B aligned.
        float4 pv[7], tv[7];
        const float4* p4 = reinterpret_cast<const float4*>(pred) + (size_t)pair * 7;
        const float4* t4 = reinterpret_cast<const float4*>(tgt)  + (size_t)pair * 7;
        #pragma unroll
        for (int j = 0; j < 7; j++) pv[j] = __ldg(&p4[j]);
        #pragma unroll
        for (int j = 0; j < 7; j++) tv[j] = __ldg(&t4[j]);

        float pf[28], tf[28];
        #pragma unroll
        for (int j = 0; j < 7; j++) {
            pf[4*j] = pv[j].x; pf[4*j+1] = pv[j].y; pf[4*j+2] = pv[j].z; pf[4*j+3] = pv[j].w;
            tf[4*j] = tv[j].x; tf[4*j+1] = tv[j].y; tf[4*j+2] = tv[j].z; tf[4*j+3] = tv[j].w;
        }

        sum  = cell_loss(pf,      tf);
        sum += cell_loss(pf + 14, tf + 14);
    }

    float bsum = block_reduce(sum);

    __shared__ bool is_last;
    if (tid == 0) {
        g_partials[blockIdx.x] = bsum;
        __threadfence();
        unsigned int v = atomicAdd(&g_count, 1u);
        is_last = (v == (unsigned int)(nblocks - 1));
    }
    __syncthreads();

    if (is_last) {
        float fs = 0.0f;
        for (int i = tid; i < nblocks; i += THREADS)
            fs += g_partials[i];
        float total = block_reduce(fs);
        if (tid == 0) {
            out[0] = total;
            g_count = 0;  // reset for next graph replay
        }
    }
}

extern "C" void kernel_launch(void* const* d_in, const int* in_sizes, int n_in,
                              void* d_out, int out_size) {
    const float* pred = (const float*)d_in[0];
    const float* tgt  = (const float*)d_in[1];
    float* out = (float*)d_out;

    int cells  = in_sizes[0] / 14;
    int pairs  = (cells + 1) / 2;
    int blocks = (pairs + THREADS - 1) / THREADS;   // 1568 for the bench shape

    yolo_loss_kernel<<<blocks, THREADS>>>(pred, tgt, out, cells, blocks);
}

// round 3
// speedup vs baseline: 1.3756x; 1.0015x over previous
#include <cuda_runtime.h>
#include <math.h>

// YOLO loss over [16384, 7, 7, 14] fp32. ~90 MB read, scalar out.
// Grid-stride persistent-style kernel, 2 cells/thread/iter, register
// double-buffered prefetch (load pair B while computing pair A) to keep
// HBM requests in flight during the long log/div compute chains.

#define THREADS    128
#define ITERS      4
#define MAX_BLOCKS 8192

__device__ float        g_partials[MAX_BLOCKS];
__device__ unsigned int g_count = 0;

static __device__ __forceinline__ float block_reduce(float v) {
    #pragma unroll
    for (int off = 16; off > 0; off >>= 1)
        v += __shfl_down_sync(0xFFFFFFFFu, v, off);
    __shared__ float warp_sums[THREADS / 32];
    int lane = threadIdx.x & 31;
    int wid  = threadIdx.x >> 5;
    if (lane == 0) warp_sums[wid] = v;
    __syncthreads();
    if (wid == 0) {
        v = (lane < (THREADS / 32)) ? warp_sums[lane] : 0.0f;
        #pragma unroll
        for (int off = (THREADS / 64); off > 0; off >>= 1)
            v += __shfl_down_sync(0xFFFFFFFFu, v, off);
    }
    return v;  // valid on thread 0
}

// Load one cell-pair (28 floats each from pred/tgt) as 7+7 float4.
static __device__ __forceinline__ void load_pair(const float4* __restrict__ p4,
                                                 const float4* __restrict__ t4,
                                                 int pair, float* pf, float* tf) {
    float4 pv[7], tv[7];
    const float4* pp = p4 + (size_t)pair * 7;
    const float4* tt = t4 + (size_t)pair * 7;
    #pragma unroll
    for (int j = 0; j < 7; j++) pv[j] = __ldg(&pp[j]);
    #pragma unroll
    for (int j = 0; j < 7; j++) tv[j] = __ldg(&tt[j]);
    #pragma unroll
    for (int j = 0; j < 7; j++) {
        pf[4*j] = pv[j].x; pf[4*j+1] = pv[j].y; pf[4*j+2] = pv[j].z; pf[4*j+3] = pv[j].w;
        tf[4*j] = tv[j].x; tf[4*j+1] = tv[j].y; tf[4*j+2] = tv[j].z; tf[4*j+3] = tv[j].w;
    }
}

static __device__ __forceinline__ float cell_loss(const float* p, const float* t) {
    const float INV_S = 1.0f / 7.0f;

    float conf_t = t[4];
    float coord  = (conf_t > 0.0f) ? 1.0f : 0.0f;

    float t_cx = t[0] * INV_S, t_cy = t[1] * INV_S;
    float t_w  = t[2],          t_h  = t[3];
    float t_l  = t_cx - 0.5f * t_w, t_r = t_cx + 0.5f * t_w;
    float t_t  = t_cy - 0.5f * t_h, t_b = t_cy + 0.5f * t_h;
    float area_t = t_w * t_h;

    float iou[2];
    #pragma unroll
    for (int b = 0; b < 2; b++) {
        float cx = p[5*b]   * INV_S;
        float cy = p[5*b+1] * INV_S;
        float w  = p[5*b+2];
        float h  = p[5*b+3];
        float pl = cx - 0.5f * w, pr = cx + 0.5f * w;
        float pt = cy - 0.5f * h, pb = cy + 0.5f * h;
        float iw = fmaxf(fminf(pr, t_r) - fmaxf(pl, t_l), 0.0f);
        float ih = fmaxf(fminf(pb, t_b) - fmaxf(pt, t_t), 0.0f);
        float inter = iw * ih;
        iou[b] = __fdividef(inter, w * h + area_t - inter);
    }

    bool  sec     = iou[1] > iou[0];          // argmax, first-index tie-break
    float max_iou = fmaxf(iou[0], iou[1]);

    float rp0 = sec ? p[5] : p[0];
    float rp1 = sec ? p[6] : p[1];
    float rp2 = sec ? p[7] : p[2];
    float rp3 = sec ? p[8] : p[3];
    float rp4 = sec ? p[9] : p[4];
    float rt0 = sec ? t[5] : t[0];
    float rt1 = sec ? t[6] : t[1];
    float rt2 = sec ? t[7] : t[2];
    float rt3 = sec ? t[8] : t[3];

    float d0 = rp0 - rt0;
    float d1 = rp1 - rt1;
    float loss_xy = d0 * d0 + d1 * d1;

    float dw = sqrtf(rp2) - sqrtf(rt2);
    float dh = sqrtf(rp3) - sqrtf(rt3);
    float loss_wh = dw * dw + dh * dh;

    float dob = rp4 - max_iou;
    float loss_obj = dob * dob;

    float loss_cls = 0.0f;
    #pragma unroll
    for (int c = 10; c < 14; c++) {
        float pc = p[c], tc = t[c];
        loss_cls -= tc * __logf(pc) + (1.0f - tc) * __logf(1.0f - pc);
    }

    float s = coord * (loss_xy + loss_wh + loss_obj + loss_cls);

    float q  = conf_t;
    float pp = p[4];
    float alpha = __fdividef(1.0f - q, 1.0f - pp);
    s += alpha * (pp - q) * __logf(pp) + (q - pp) * __logf(1.0f - pp);
    return s;
}

__global__ __launch_bounds__(THREADS)
void yolo_loss_kernel(const float* __restrict__ pred,
                      const float* __restrict__ tgt,
                      float* __restrict__ out,
                      int pairs, int nblocks) {
    const float4* p4 = reinterpret_cast<const float4*>(pred);
    const float4* t4 = reinterpret_cast<const float4*>(tgt);

    int tid    = threadIdx.x;
    int stride = gridDim.x * THREADS;
    int i      = blockIdx.x * THREADS + tid;
    float sum  = 0.0f;

    float pA[28], tA[28], pB[28], tB[28];

    bool vA = (i < pairs);
    if (vA) load_pair(p4, t4, i, pA, tA);

    while (vA) {
        int  j  = i + stride;
        bool vB = (j < pairs);
        if (vB) load_pair(p4, t4, j, pB, tB);      // prefetch B
        sum += cell_loss(pA, tA) + cell_loss(pA + 14, tA + 14);
        if (vB) {
            int k = j + stride;
            vA = (k < pairs);
            if (vA) load_pair(p4, t4, k, pA, tA);  // prefetch A
            sum += cell_loss(pB, tB) + cell_loss(pB + 14, tB + 14);
            i = k;
        } else {
            vA = false;
        }
    }

    float bsum = block_reduce(sum);

    __shared__ bool is_last;
    if (tid == 0) {
        g_partials[blockIdx.x] = bsum;
        __threadfence();
        unsigned int v = atomicAdd(&g_count, 1u);
        is_last = (v == (unsigned int)(nblocks - 1));
    }
    __syncthreads();

    if (is_last) {
        float fs = 0.0f;
        for (int b = tid; b < nblocks; b += THREADS)
            fs += g_partials[b];
        float total = block_reduce(fs);
        if (tid == 0) {
            out[0] = total;
            g_count = 0;  // reset for next graph replay
        }
    }
}

extern "C" void kernel_launch(void* const* d_in, const int* in_sizes, int n_in,
                              void* d_out, int out_size) {
    const float* pred = (const float*)d_in[0];
    const float* tgt  = (const float*)d_in[1];
    float* out = (float*)d_out;

    int cells = in_sizes[0] / 14;
    int pairs = (cells + 1) / 2;                       // 401408
    int blocks = (pairs + THREADS * ITERS - 1) / (THREADS * ITERS);  // 784
    if (blocks > MAX_BLOCKS) blocks = MAX_BLOCKS;

    yolo_loss_kernel<<<blocks, THREADS>>>(pred, tgt, out, pairs, blocks);
}

// round 5
// speedup vs baseline: 1.3924x; 1.0122x over previous
#include <cuda_runtime.h>
#include <cstdint>
#include <math.h>

// YOLO loss over [16384, 7, 7, 14] fp32 (~90 MB read, scalar out).
// cp.async (LDGSTS) double-buffered smem pipeline: each stage stages
// 256 cells of pred+tgt (28 KB) into shared memory with fire-and-forget
// 16B copies, so DRAM requests stay in flight during the log/div compute.

#define THREADS        256
#define CELLS_PER_STG  256
#define STG_BYTES_ONE  (CELLS_PER_STG * 56)        // 14336 B per array
#define STG_BYTES      (2 * STG_BYTES_ONE)         // 28672 B per stage
#define NSTAGES        2
#define SMEM_BYTES     (NSTAGES * STG_BYTES)       // 57344 B
#define CHUNKS_PER_STG (STG_BYTES / 16)            // 1792 16B chunks
#define MAX_BLOCKS     8192

__device__ float        g_partials[MAX_BLOCKS];
__device__ unsigned int g_count = 0;

static __device__ __forceinline__ void cp_async16(uint32_t smem_addr, const void* gptr) {
    asm volatile("cp.async.cg.shared.global [%0], [%1], 16;\n"
                 :: "r"(smem_addr), "l"(gptr));
}
static __device__ __forceinline__ void cp_commit() {
    asm volatile("cp.async.commit_group;\n" ::: "memory");
}
template <int N>
static __device__ __forceinline__ void cp_wait() {
    asm volatile("cp.async.wait_group %0;\n" :: "n"(N) : "memory");
}

static __device__ __forceinline__ float block_reduce(float v) {
    #pragma unroll
    for (int off = 16; off > 0; off >>= 1)
        v += __shfl_down_sync(0xFFFFFFFFu, v, off);
    __shared__ float warp_sums[THREADS / 32];
    int lane = threadIdx.x & 31;
    int wid  = threadIdx.x >> 5;
    if (lane == 0) warp_sums[wid] = v;
    __syncthreads();
    if (wid == 0) {
        v = (lane < (THREADS / 32)) ? warp_sums[lane] : 0.0f;
        #pragma unroll
        for (int off = (THREADS / 64); off > 0; off >>= 1)
            v += __shfl_down_sync(0xFFFFFFFFu, v, off);
    }
    return v;  // valid on thread 0
}

static __device__ __forceinline__ float cell_loss(const float* __restrict__ p,
                                                  const float* __restrict__ t) {
    const float INV_S = 1.0f / 7.0f;

    float conf_t = t[4];
    float coord  = (conf_t > 0.0f) ? 1.0f : 0.0f;

    float t_cx = t[0] * INV_S, t_cy = t[1] * INV_S;
    float t_w  = t[2],          t_h  = t[3];
    float t_l  = t_cx - 0.5f * t_w, t_r = t_cx + 0.5f * t_w;
    float t_t  = t_cy - 0.5f * t_h, t_b = t_cy + 0.5f * t_h;
    float area_t = t_w * t_h;

    float iou[2];
    #pragma unroll
    for (int b = 0; b < 2; b++) {
        float cx = p[5*b]   * INV_S;
        float cy = p[5*b+1] * INV_S;
        float w  = p[5*b+2];
        float h  = p[5*b+3];
        float pl = cx - 0.5f * w, pr = cx + 0.5f * w;
        float pt = cy - 0.5f * h, pb = cy + 0.5f * h;
        float iw = fmaxf(fminf(pr, t_r) - fmaxf(pl, t_l), 0.0f);
        float ih = fmaxf(fminf(pb, t_b) - fmaxf(pt, t_t), 0.0f);
        float inter = iw * ih;
        iou[b] = __fdividef(inter, w * h + area_t - inter);
    }

    bool  sec     = iou[1] > iou[0];          // argmax, first-index tie-break
    float max_iou = fmaxf(iou[0], iou[1]);

    float rp0 = sec ? p[5] : p[0];
    float rp1 = sec ? p[6] : p[1];
    float rp2 = sec ? p[7] : p[2];
    float rp3 = sec ? p[8] : p[3];
    float rp4 = sec ? p[9] : p[4];
    float rt0 = sec ? t[5] : t[0];
    float rt1 = sec ? t[6] : t[1];
    float rt2 = sec ? t[7] : t[2];
    float rt3 = sec ? t[8] : t[3];

    float d0 = rp0 - rt0;
    float d1 = rp1 - rt1;
    float loss_xy = d0 * d0 + d1 * d1;

    float dw = sqrtf(rp2) - sqrtf(rt2);
    float dh = sqrtf(rp3) - sqrtf(rt3);
    float loss_wh = dw * dw + dh * dh;

    float dob = rp4 - max_iou;
    float loss_obj = dob * dob;

    float loss_cls = 0.0f;
    #pragma unroll
    for (int c = 10; c < 14; c++) {
        float pc = p[c], tc = t[c];
        loss_cls -= tc * __logf(pc) + (1.0f - tc) * __logf(1.0f - pc);
    }

    float s = coord * (loss_xy + loss_wh + loss_obj + loss_cls);

    float q  = conf_t;
    float pp = p[4];
    float alpha = __fdividef(1.0f - q, 1.0f - pp);
    s += alpha * (pp - q) * __logf(pp) + (q - pp) * __logf(1.0f - pp);
    return s;
}

// Stage `st` (256 cells) of pred+tgt into smem buffer `buf`.
static __device__ __forceinline__ void prefetch_stage(
        const char* __restrict__ pred_b, const char* __restrict__ tgt_b,
        uint32_t smem_base_u32, int buf, int st, size_t total_bytes_one) {
    uint32_t dst = smem_base_u32 + buf * STG_BYTES;
    size_t goff  = (size_t)st * STG_BYTES_ONE;
    #pragma unroll
    for (int k = 0; k < CHUNKS_PER_STG / THREADS; k++) {   // 7 iters
        int i = threadIdx.x + k * THREADS;                 // [0, 1792)
        bool is_t = (i >= STG_BYTES_ONE / 16);
        int  j16  = is_t ? (i - STG_BYTES_ONE / 16) : i;
        size_t gb = goff + (size_t)j16 * 16;
        if (gb < total_bytes_one) {
            const char* src = (is_t ? tgt_b : pred_b) + gb;
            cp_async16(dst + (uint32_t)i * 16, src);
        }
    }
}

__global__ __launch_bounds__(THREADS)
void yolo_loss_kernel(const float* __restrict__ pred,
                      const float* __restrict__ tgt,
                      float* __restrict__ out,
                      int cells, int nstages_total, int nblocks) {
    extern __shared__ float sh[];
    uint32_t sh_u32;
    asm("{ .reg .u64 t; cvta.to.shared.u64 t, %1; cvt.u32.u64 %0, t; }"
        : "=r"(sh_u32) : "l"(sh));

    const char* pred_b = (const char*)pred;
    const char* tgt_b  = (const char*)tgt;
    size_t total_bytes_one = (size_t)cells * 56;

    int tid = threadIdx.x;
    float sum = 0.0f;

    int st  = blockIdx.x;
    int buf = 0;
    if (st < nstages_total) {
        prefetch_stage(pred_b, tgt_b, sh_u32, buf, st, total_bytes_one);
        cp_commit();
    }

    while (st < nstages_total) {
        int nxt = st + gridDim.x;
        if (nxt < nstages_total) {
            prefetch_stage(pred_b, tgt_b, sh_u32, buf ^ 1, nxt, total_bytes_one);
            cp_commit();
            cp_wait<1>();          // current stage done, next may be in flight
        } else {
            cp_wait<0>();
        }
        __syncthreads();

        int cell = st * CELLS_PER_STG + tid;
        if (cell < cells) {
            const float* base = sh + (size_t)buf * (STG_BYTES / 4);
            const float* p = base + tid * 14;
            const float* t = base + (STG_BYTES_ONE / 4) + tid * 14;
            sum += cell_loss(p, t);
        }
        __syncthreads();           // buffer consumed before next overwrite
        st  = nxt;
        buf ^= 1;
    }

    float bsum = block_reduce(sum);

    __shared__ bool is_last;
    if (tid == 0) {
        g_partials[blockIdx.x] = bsum;
        __threadfence();
        unsigned int v = atomicAdd(&g_count, 1u);
        is_last = (v == (unsigned int)(nblocks - 1));
    }
    __syncthreads();

    if (is_last) {
        float fs = 0.0f;
        for (int b = tid; b < nblocks; b += THREADS)
            fs += g_partials[b];
        float total = block_reduce(fs);
        if (tid == 0) {
            out[0] = total;
            g_count = 0;  // reset for next graph replay
        }
    }
}

extern "C" void kernel_launch(void* const* d_in, const int* in_sizes, int n_in,
                              void* d_out, int out_size) {
    const float* pred = (const float*)d_in[0];
    const float* tgt  = (const float*)d_in[1];
    float* out = (float*)d_out;

    int cells = in_sizes[0] / 14;                          // 802816
    int nstages_total = (cells + CELLS_PER_STG - 1) / CELLS_PER_STG;  // 3136

    int blocks = 448;                                      // 7 stages/block exactly
    if (blocks > nstages_total) blocks = nstages_total;
    if (blocks > MAX_BLOCKS) blocks = MAX_BLOCKS;

    static bool attr_set = false;
    if (!attr_set) {
        cudaFuncSetAttribute(yolo_loss_kernel,
                             cudaFuncAttributeMaxDynamicSharedMemorySize,
                             SMEM_BYTES);
        attr_set = true;
    }

    yolo_loss_kernel<<<blocks, THREADS, SMEM_BYTES>>>(pred, tgt, out,
                                                      cells, nstages_total, blocks);
}